// round 1
// baseline (speedup 1.0000x reference)
#include <cuda_runtime.h>
#include <math.h>

#define NPIX 512
#define PARTS 8
#define MAXPARTS 16
#define INF_F 1000000000.0f
#define MU_F 1e-8f
#define THRESH 0.05f

// One CTA per batch. Only the pixel-space bounding box of the valid disc
// (dist <= r in map coords) is ever touched: everything else contributes INF
// to the segment-min, i.e. nothing. Bin index is computed by exact octant
// classification (signs + |dx| vs |dy|), no atan2 needed.
__global__ __launch_bounds__(256) void pcl_kernel(
    const float* __restrict__ seg_maps,   // (B, N, N)
    const float* __restrict__ paras,      // (B, 4): wx, wy, bx, by
    const float* __restrict__ traj,       // (B, 8, 2)
    const float* __restrict__ cpos,       // (B, 1, 2)
    float* __restrict__ out)              // (B, 16, 3)
{
    const int b = blockIdx.x;
    const int tid = threadIdx.x;

    __shared__ unsigned smin[PARTS];
    if (tid < PARTS) smin[tid] = __float_as_uint(INF_F);
    __syncthreads();

    const float wx = paras[b * 4 + 0];
    const float wy = paras[b * 4 + 1];
    const float bx = paras[b * 4 + 2];
    const float by = paras[b * 4 + 3];
    const float cx = cpos[b * 2 + 0];
    const float cy = cpos[b * 2 + 1];

    // moving vector: _obs[-1]-_obs[0] == traj[7]-traj[0] (current_pos cancels)
    const float mvx = traj[b * 16 + 14] - traj[b * 16 + 0];
    const float mvy = traj[b * 16 + 15] - traj[b * 16 + 1];
    const float mlen = sqrtf(mvx * mvx + mvy * mvy);
    const float r = 2.0f * mlen;   // VISION_RADIUS * moving_length
    const float r2 = r * r;

    // pixel-space bounding box of the disc |map_pos - c| <= r
    // map_x = (px - bx)/wx  =>  px in [bx + wx*(cx-r), bx + wx*(cx+r)]
    int x0 = max(0, (int)floorf(bx + wx * (cx - r)) - 1);
    int x1 = min(NPIX - 1, (int)ceilf(bx + wx * (cx + r)) + 1);
    int y0 = max(0, (int)floorf(by + wy * (cy - r)) - 1);
    int y1 = min(NPIX - 1, (int)ceilf(by + wy * (cy + r)) + 1);

    if (x1 >= x0 && y1 >= y0) {
        const int bw = y1 - y0 + 1;
        const int total = (x1 - x0 + 1) * bw;
        const float* __restrict__ sm = seg_maps + (size_t)b * NPIX * NPIX;

        for (int i = tid; i < total; i += blockDim.x) {
            const int rr = i / bw;
            const int cc = i - rr * bw;
            const int px = x0 + rr;
            const int py = y0 + cc;

            const float dx = ((float)px - bx) / wx - cx;
            const float dy = ((float)py - by) / wy - cy;
            const float d2 = dx * dx + dy * dy;

            if (d2 <= r2 * 1.0009765625f) {   // loose prefilter
                const float dist = sqrtf(d2);
                if (dist <= r) {              // exact reference condition
                    const float m = sm[px * NPIX + py];
                    if (m > THRESH) {         // valid = ~safe
                        const float e = (dist + MU_F) / (m + MU_F);

                        // exact octant of atan2(dx, dy) mod 2pi, bins of pi/4
                        int bin;
                        if (dy > 0.0f) {
                            if (dx >= 0.0f) bin = (dx < dy) ? 0 : 1;
                            else            bin = (-dx <= dy) ? 7 : 6;
                        } else if (dy < 0.0f) {
                            if (dx > 0.0f)  bin = (dx > -dy) ? 2 : 3;
                            else            bin = (dx > dy) ? 4 : 5;
                        } else {
                            bin = (dx > 0.0f) ? 2 : ((dx < 0.0f) ? 6 : 0);
                        }
                        // all candidates >= 0, so uint order == float order
                        atomicMin(&smin[bin], __float_as_uint(e));
                    }
                }
            }
        }
    }
    __syncthreads();

    // format output: (B, 16, 3); partitions 8..15 are zero padding
    if (tid < MAXPARTS) {
        float v0 = 0.0f, v1 = 0.0f, v2 = 0.0f;
        if (tid < PARTS) {
            const float md = fminf(__uint_as_float(smin[tid]), INF_F);
            if (md < INF_F) {
                v0 = mlen;                                     // f_velocity
                v1 = md;                                       // f_min_distance
                v2 = 6.283185307179586f * ((float)tid + 0.5f) / 8.0f; // f_direction
            }
        }
        float* ob = out + (size_t)b * MAXPARTS * 3 + tid * 3;
        ob[0] = v0;
        ob[1] = v1;
        ob[2] = v2;
    }
}

extern "C" void kernel_launch(void* const* d_in, const int* in_sizes, int n_in,
                              void* d_out, int out_size) {
    const float* seg_maps = (const float*)d_in[0];  // (128, 512, 512)
    const float* paras    = (const float*)d_in[1];  // (128, 4)
    const float* traj     = (const float*)d_in[2];  // (128, 8, 2)
    const float* cpos     = (const float*)d_in[3];  // (128, 1, 2)
    // d_in[4] = map_pos_pixel: derived analytically from the pixel index, unused
    float* out = (float*)d_out;                     // (128, 16, 3)

    const int B = in_sizes[1] / 4;                  // 128
    pcl_kernel<<<B, 256>>>(seg_maps, paras, traj, cpos, out);
}

// round 2
// speedup vs baseline: 1.4250x; 1.4250x over previous
#include <cuda_runtime.h>
#include <math.h>

#define NPIX 512
#define PARTS 8
#define MAXPARTS 16
#define INF_F 1000000000.0f
#define MU_F 1e-8f
#define THRESH 0.05f

// One CTA (1024 threads) per batch. Only the pixel-space bounding box of the
// valid disc (dist <= r in map coords) is touched. Warp-per-row, lane-per-col
// tiling -> ~2x2 strided iterations for a typical ~45x45 box, loads issued
// unconditionally for max MLP. Per-thread 8-bin register mins, warp butterfly
// reduction, then at most 8 shared atomics per warp.
__global__ __launch_bounds__(1024) void pcl_kernel(
    const float* __restrict__ seg_maps,   // (B, N, N)
    const float* __restrict__ paras,      // (B, 4): wx, wy, bx, by
    const float* __restrict__ traj,       // (B, 8, 2)
    const float* __restrict__ cpos,       // (B, 1, 2)
    float* __restrict__ out)              // (B, 16, 3)
{
    const int b    = blockIdx.x;
    const int tid  = threadIdx.x;
    const int lane = tid & 31;
    const int warp = tid >> 5;            // 32 warps

    __shared__ unsigned smin[PARTS];
    if (tid < PARTS) smin[tid] = __float_as_uint(INF_F);

    // All scalar params issued up front (independent loads, one DRAM round)
    const float wx  = __ldg(&paras[b * 4 + 0]);
    const float wy  = __ldg(&paras[b * 4 + 1]);
    const float bx  = __ldg(&paras[b * 4 + 2]);
    const float by  = __ldg(&paras[b * 4 + 3]);
    const float cx  = __ldg(&cpos[b * 2 + 0]);
    const float cy  = __ldg(&cpos[b * 2 + 1]);
    const float t0x = __ldg(&traj[b * 16 + 0]);
    const float t0y = __ldg(&traj[b * 16 + 1]);
    const float t7x = __ldg(&traj[b * 16 + 14]);
    const float t7y = __ldg(&traj[b * 16 + 15]);

    // moving vector: _obs[-1]-_obs[0] == traj[7]-traj[0] (current_pos cancels)
    const float mvx  = t7x - t0x;
    const float mvy  = t7y - t0y;
    const float mlen = sqrtf(mvx * mvx + mvy * mvy);
    const float r    = 2.0f * mlen;       // VISION_RADIUS * moving_length

    // pixel-space bounding box of the disc |map_pos - c| <= r
    const int x0 = max(0, (int)floorf(bx + wx * (cx - r)) - 1);
    const int x1 = min(NPIX - 1, (int)ceilf(bx + wx * (cx + r)) + 1);
    const int y0 = max(0, (int)floorf(by + wy * (cy - r)) - 1);
    const int y1 = min(NPIX - 1, (int)ceilf(by + wy * (cy + r)) + 1);

    __syncthreads();   // smem init visible

    float lmin[PARTS];
    #pragma unroll
    for (int k = 0; k < PARTS; k++) lmin[k] = INF_F;

    const int H = x1 - x0 + 1;
    const int W = y1 - y0 + 1;

    if (H > 0 && W > 0) {
        const float* __restrict__ sm = seg_maps + (size_t)b * NPIX * NPIX;

        for (int rr = warp; rr < H; rr += 32) {
            const int px = x0 + rr;
            const float dx  = ((float)px - bx) / wx - cx;
            const float dx2 = dx * dx;
            const float* __restrict__ rowp = sm + px * NPIX + y0;

            for (int cc = lane; cc < W; cc += 32) {
                const float m = __ldg(rowp + cc);         // unconditional load
                const int   py = y0 + cc;
                const float dy = ((float)py - by) / wy - cy;
                const float d2 = dx2 + dy * dy;
                const float dist = sqrtf(d2);

                if (dist <= r && m > THRESH) {
                    const float e = (dist + MU_F) / (m + MU_F);

                    // exact octant of atan2(dx, dy) mod 2pi, bins of pi/4
                    int bin;
                    if (dy > 0.0f) {
                        if (dx >= 0.0f) bin = (dx < dy) ? 0 : 1;
                        else            bin = (-dx <= dy) ? 7 : 6;
                    } else if (dy < 0.0f) {
                        if (dx > 0.0f)  bin = (dx > -dy) ? 2 : 3;
                        else            bin = (dx > dy) ? 4 : 5;
                    } else {
                        bin = (dx > 0.0f) ? 2 : ((dx < 0.0f) ? 6 : 0);
                    }

                    // static-index predicated update (no local-mem spill)
                    #pragma unroll
                    for (int k = 0; k < PARTS; k++)
                        if (bin == k) lmin[k] = fminf(lmin[k], e);
                }
            }
        }
    }

    // warp butterfly min-reduce per bin
    #pragma unroll
    for (int k = 0; k < PARTS; k++) {
        #pragma unroll
        for (int off = 16; off > 0; off >>= 1)
            lmin[k] = fminf(lmin[k], __shfl_xor_sync(0xffffffffu, lmin[k], off));
    }

    // one lane per bin commits (skip INF): <=8 ATOMS per warp, distinct banks
    #pragma unroll
    for (int k = 0; k < PARTS; k++)
        if (lane == k && lmin[k] < INF_F)
            atomicMin(&smin[k], __float_as_uint(lmin[k]));

    __syncthreads();

    // format output: (B, 16, 3); partitions 8..15 are zero padding
    if (tid < MAXPARTS) {
        float v0 = 0.0f, v1 = 0.0f, v2 = 0.0f;
        if (tid < PARTS) {
            const float md = fminf(__uint_as_float(smin[tid]), INF_F);
            if (md < INF_F) {
                v0 = mlen;                                            // f_velocity
                v1 = md;                                              // f_min_distance
                v2 = 6.283185307179586f * ((float)tid + 0.5f) / 8.0f; // f_direction
            }
        }
        float* ob = out + (size_t)b * MAXPARTS * 3 + tid * 3;
        ob[0] = v0;
        ob[1] = v1;
        ob[2] = v2;
    }
}

extern "C" void kernel_launch(void* const* d_in, const int* in_sizes, int n_in,
                              void* d_out, int out_size) {
    const float* seg_maps = (const float*)d_in[0];  // (128, 512, 512)
    const float* paras    = (const float*)d_in[1];  // (128, 4)
    const float* traj     = (const float*)d_in[2];  // (128, 8, 2)
    const float* cpos     = (const float*)d_in[3];  // (128, 1, 2)
    // d_in[4] = map_pos_pixel: derived analytically from the pixel index, unused
    float* out = (float*)d_out;                     // (128, 16, 3)

    const int B = in_sizes[1] / 4;                  // 128
    pcl_kernel<<<B, 1024>>>(seg_maps, paras, traj, cpos, out);
}

// round 3
// speedup vs baseline: 2.1007x; 1.4742x over previous
#include <cuda_runtime.h>
#include <math.h>

#define NPIX 512
#define BMAX 128
#define PARTS 8
#define MAXPARTS 16
#define SLICES 8
#define INF_F 1000000000.0f
#define MU_F 1e-8f
#define THRESH 0.05f

// Cross-CTA reduction state. Zero-init at module load; self-resetting each
// launch (last CTA per batch clears after formatting), so graph replays are
// deterministic. g_min stores ~bits(e) and uses atomicMax: for e >= 0, float
// order == uint order on the bit pattern, so max(~bits) == min(e), and the
// all-zero initial state means "no obstacle" (any real update is > 0).
__device__ unsigned g_min[BMAX * PARTS];
__device__ unsigned g_cnt[BMAX];

// Grid (B, SLICES), 128 threads (4 warps) per CTA. Each slice CTA handles
// rows rr ≡ slice (mod SLICES) of the batch's valid-disc bounding box.
// Lanes span 32 consecutive columns (coalesced), warps+row-loop span rows.
__global__ __launch_bounds__(128) void pcl_kernel(
    const float* __restrict__ seg_maps,   // (B, N, N)
    const float* __restrict__ paras,      // (B, 4): wx, wy, bx, by
    const float* __restrict__ traj,       // (B, 8, 2)
    const float* __restrict__ cpos,       // (B, 1, 2)
    float* __restrict__ out)              // (B, 16, 3)
{
    const int b    = blockIdx.x;
    const int s    = blockIdx.y;
    const int tid  = threadIdx.x;
    const int lane = tid & 31;
    const int warp = tid >> 5;            // 0..3

    // scalar params (independent loads, one memory round)
    const float wx  = __ldg(&paras[b * 4 + 0]);
    const float wy  = __ldg(&paras[b * 4 + 1]);
    const float bx  = __ldg(&paras[b * 4 + 2]);
    const float by  = __ldg(&paras[b * 4 + 3]);
    const float cx  = __ldg(&cpos[b * 2 + 0]);
    const float cy  = __ldg(&cpos[b * 2 + 1]);
    const float t0x = __ldg(&traj[b * 16 + 0]);
    const float t0y = __ldg(&traj[b * 16 + 1]);
    const float t7x = __ldg(&traj[b * 16 + 14]);
    const float t7y = __ldg(&traj[b * 16 + 15]);

    // moving vector: _obs[-1]-_obs[0] == traj[7]-traj[0] (current_pos cancels)
    const float mvx  = t7x - t0x;
    const float mvy  = t7y - t0y;
    const float mlen = sqrtf(mvx * mvx + mvy * mvy);
    const float r    = 2.0f * mlen;       // VISION_RADIUS * moving_length

    // pixel-space bounding box of the disc |map_pos - c| <= r
    const int x0 = max(0, (int)floorf(bx + wx * (cx - r)) - 1);
    const int x1 = min(NPIX - 1, (int)ceilf(bx + wx * (cx + r)) + 1);
    const int y0 = max(0, (int)floorf(by + wy * (cy - r)) - 1);
    const int y1 = min(NPIX - 1, (int)ceilf(by + wy * (cy + r)) + 1);

    const int H = x1 - x0 + 1;
    const int W = y1 - y0 + 1;

    float lmin[PARTS];
    #pragma unroll
    for (int k = 0; k < PARTS; k++) lmin[k] = INF_F;

    if (H > 0 && W > 0) {
        const float* __restrict__ sm = seg_maps + (size_t)b * NPIX * NPIX;
        const float inv_wx = 1.0f / wx;
        const float inv_wy = 1.0f / wy;

        // columns outer (per-lane), rows inner (warp-uniform -> coalesced)
        for (int cc = lane; cc < W; cc += 32) {
            const int   py  = y0 + cc;
            const float dy  = ((float)py - by) * inv_wy - cy;
            const float dy2 = dy * dy;
            const float ndy = -dy;

            for (int rr = s + SLICES * warp; rr < H; rr += SLICES * 4) {
                const int   px = x0 + rr;
                const float m  = __ldg(sm + px * NPIX + py);   // load first
                const float dx = ((float)px - bx) * inv_wx - cx;
                const float d2 = fmaf(dx, dx, dy2);
                const float dist = sqrtf(d2);

                if (dist <= r && m > THRESH) {
                    const float e = __fdividef(dist + MU_F, m + MU_F);

                    // exact octant of atan2(dx, dy) mod 2pi (branchless selects)
                    const int bin =
                        (dy > 0.0f) ? ((dx >= 0.0f) ? ((dx <  dy) ? 0 : 1)
                                                    : ((-dx <= dy) ? 7 : 6))
                      : (dy < 0.0f) ? ((dx > 0.0f)  ? ((dx > ndy) ? 2 : 3)
                                                    : ((dx >  dy) ? 4 : 5))
                                    : ((dx > 0.0f) ? 2 : ((dx < 0.0f) ? 6 : 0));

                    #pragma unroll
                    for (int k = 0; k < PARTS; k++)
                        if (bin == k) lmin[k] = fminf(lmin[k], e);
                }
            }
        }
    }

    // warp butterfly min-reduce per bin
    #pragma unroll
    for (int k = 0; k < PARTS; k++) {
        #pragma unroll
        for (int off = 16; off > 0; off >>= 1)
            lmin[k] = fminf(lmin[k], __shfl_xor_sync(0xffffffffu, lmin[k], off));
    }

    // lane k commits bin k (skip empty): <=8 REDG per warp, distinct addrs
    #pragma unroll
    for (int k = 0; k < PARTS; k++)
        if (lane == k && lmin[k] < INF_F)
            atomicMax(&g_min[b * PARTS + k], ~__float_as_uint(lmin[k]));

    // arrival: last slice CTA of this batch formats the output
    __threadfence();
    __syncthreads();
    __shared__ unsigned sprev;
    if (tid == 0) sprev = atomicAdd(&g_cnt[b], 1u);
    __syncthreads();

    if (sprev == SLICES - 1) {
        __threadfence();
        if (tid < MAXPARTS) {
            float v0 = 0.0f, v1 = 0.0f, v2 = 0.0f;
            if (tid < PARTS) {
                const unsigned g = *(volatile unsigned*)&g_min[b * PARTS + tid];
                if (g != 0u) {
                    v0 = mlen;                                            // f_velocity
                    v1 = __uint_as_float(~g);                             // f_min_distance
                    v2 = 6.283185307179586f * ((float)tid + 0.5f) / 8.0f; // f_direction
                }
                *(volatile unsigned*)&g_min[b * PARTS + tid] = 0u;        // reset for next replay
            }
            if (tid == 0) *(volatile unsigned*)&g_cnt[b] = 0u;            // reset counter
            float* ob = out + (size_t)b * MAXPARTS * 3 + tid * 3;
            ob[0] = v0;
            ob[1] = v1;
            ob[2] = v2;
        }
    }
}

extern "C" void kernel_launch(void* const* d_in, const int* in_sizes, int n_in,
                              void* d_out, int out_size) {
    const float* seg_maps = (const float*)d_in[0];  // (128, 512, 512)
    const float* paras    = (const float*)d_in[1];  // (128, 4)
    const float* traj     = (const float*)d_in[2];  // (128, 8, 2)
    const float* cpos     = (const float*)d_in[3];  // (128, 1, 2)
    // d_in[4] = map_pos_pixel: derived analytically from the pixel index, unused
    float* out = (float*)d_out;                     // (128, 16, 3)

    const int B = in_sizes[1] / 4;                  // 128
    dim3 grid(B, SLICES);
    pcl_kernel<<<grid, 128>>>(seg_maps, paras, traj, cpos, out);
}

// round 4
// speedup vs baseline: 2.2208x; 1.0571x over previous
#include <cuda_runtime.h>
#include <math.h>

#define NPIX 512
#define BMAX 128
#define PARTS 8
#define MAXPARTS 16
#define SLICES 8
#define CTA 128
#define INF_F 1000000000.0f
#define MU_F 1e-8f
#define THRESH 0.05f

// Cross-CTA reduction state. Zero-init at module load; self-resetting each
// launch (last CTA per batch clears after formatting). g_min stores ~bits(e),
// atomicMax: for e >= 0 float order == uint order, so max(~bits) == min(e);
// all-zero initial state means "no obstacle".
__device__ unsigned g_min[BMAX * PARTS];
__device__ unsigned g_cnt[BMAX];

// Grid (B, SLICES), 128 threads per CTA. The batch's valid-disc bounding box
// is covered by float4 pixel-groups indexed with a pow-2 flattened mapping
// (row = g >> lg, col4 = (g & (Wq-1)) << 2), strided across the 1024 threads
// of the batch's 8 slice-CTAs. Per-pixel bin mins go to a private smem slot
// sbin[bin][tid]; warps then reduce two bins each and commit via global
// atomicMax.
__global__ __launch_bounds__(CTA) void pcl_kernel(
    const float* __restrict__ seg_maps,   // (B, N, N)
    const float* __restrict__ paras,      // (B, 4): wx, wy, bx, by
    const float* __restrict__ traj,       // (B, 8, 2)
    const float* __restrict__ cpos,       // (B, 1, 2)
    float* __restrict__ out)              // (B, 16, 3)
{
    const int b    = blockIdx.x;
    const int s    = blockIdx.y;
    const int tid  = threadIdx.x;
    const int lane = tid & 31;
    const int warp = tid >> 5;            // 0..3

    __shared__ float sbin[PARTS * CTA];
    #pragma unroll
    for (int k = 0; k < PARTS; k++) sbin[k * CTA + tid] = INF_F;

    // scalar params (independent loads, one memory round)
    const float wx  = __ldg(&paras[b * 4 + 0]);
    const float wy  = __ldg(&paras[b * 4 + 1]);
    const float bx  = __ldg(&paras[b * 4 + 2]);
    const float by  = __ldg(&paras[b * 4 + 3]);
    const float cx  = __ldg(&cpos[b * 2 + 0]);
    const float cy  = __ldg(&cpos[b * 2 + 1]);
    const float t0x = __ldg(&traj[b * 16 + 0]);
    const float t0y = __ldg(&traj[b * 16 + 1]);
    const float t7x = __ldg(&traj[b * 16 + 14]);
    const float t7y = __ldg(&traj[b * 16 + 15]);

    // moving vector: _obs[-1]-_obs[0] == traj[7]-traj[0] (current_pos cancels)
    const float mvx  = t7x - t0x;
    const float mvy  = t7y - t0y;
    const float mlen = sqrtf(mvx * mvx + mvy * mvy);
    const float r    = 2.0f * mlen;       // VISION_RADIUS * moving_length

    // pixel-space bounding box of the disc |map_pos - c| <= r
    const int x0 = max(0, (int)floorf(bx + wx * (cx - r)) - 1);
    const int x1 = min(NPIX - 1, (int)ceilf(bx + wx * (cx + r)) + 1);
    const int y0 = max(0, (int)floorf(by + wy * (cy - r)) - 1);
    const int y1 = min(NPIX - 1, (int)ceilf(by + wy * (cy + r)) + 1);

    const float inv_wx = 1.0f / wx;
    const float inv_wy = 1.0f / wy;
    const float cxx = -bx * inv_wx - cx;  // dx = px*inv_wx + cxx
    const float cyy = -by * inv_wy - cy;  // dy = py*inv_wy + cyy

    const int y0a = y0 & ~3;              // 4-align (extra pixels fail dist<=r)
    int Gtot = 0, lgWq = 0, Wqm = 0;
    if (x1 >= x0 && y1 >= y0) {
        const int groups = (y1 - y0a + 4) >> 2;       // ceil width / 4
        int Wq = 1;
        while (Wq < groups) Wq <<= 1;                 // pow-2 groups per row
        lgWq = 31 - __clz(Wq);
        Wqm  = Wq - 1;
        Gtot = Wq * (x1 - x0 + 1);
    }

    __syncthreads();   // sbin init visible

    const float* __restrict__ sm = seg_maps + (size_t)b * NPIX * NPIX;

    for (int g = s * CTA + tid; g < Gtot; g += SLICES * CTA) {
        const int row = g >> lgWq;
        const int py0 = y0a + ((g & Wqm) << 2);       // 4-aligned column base
        const int px  = x0 + row;

        // aligned groups are fully inside or fully outside the image
        const bool inimg = (py0 < NPIX);
        const float4 m4 = *(const float4*)(sm + px * NPIX + (inimg ? py0 : NPIX - 4));

        const float dx  = fmaf((float)px, inv_wx, cxx);
        const float dx2 = dx * dx;
        float dy = fmaf((float)py0, inv_wy, cyy);

        const float mm[4] = {m4.x, m4.y, m4.z, m4.w};
        #pragma unroll
        for (int j = 0; j < 4; j++) {
            const float d2   = fmaf(dy, dy, dx2);
            const float dist = sqrtf(d2);
            const float m    = mm[j];

            if (inimg && dist <= r && m > THRESH) {
                const float e = __fdividef(dist + MU_F, m + MU_F);

                // exact octant of atan2(dx, dy) mod 2pi (select chain)
                const int bin =
                    (dy > 0.0f) ? ((dx >= 0.0f) ? ((dx <  dy) ? 0 : 1)
                                                : ((-dx <= dy) ? 7 : 6))
                  : (dy < 0.0f) ? ((dx > 0.0f)  ? ((dx > -dy) ? 2 : 3)
                                                : ((dx >  dy) ? 4 : 5))
                                : ((dx > 0.0f) ? 2 : ((dx < 0.0f) ? 6 : 0));

                float* slot = &sbin[bin * CTA + tid]; // bank == lane: conflict-free
                *slot = fminf(*slot, e);
            }
            dy += inv_wy;
        }
    }

    __syncthreads();

    // warp w reduces bins 2w and 2w+1
    #pragma unroll
    for (int kk = 0; kk < 2; kk++) {
        const int k = warp * 2 + kk;
        const float* p = &sbin[k * CTA];
        float v = fminf(fminf(p[lane], p[lane + 32]),
                        fminf(p[lane + 64], p[lane + 96]));
        #pragma unroll
        for (int off = 16; off > 0; off >>= 1)
            v = fminf(v, __shfl_xor_sync(0xffffffffu, v, off));
        if (lane == 0 && v < INF_F)
            atomicMax(&g_min[b * PARTS + k], ~__float_as_uint(v));
    }

    // arrival: last slice CTA of this batch formats the output
    __threadfence();
    __syncthreads();
    __shared__ unsigned sprev;
    if (tid == 0) sprev = atomicAdd(&g_cnt[b], 1u);
    __syncthreads();

    if (sprev == SLICES - 1) {
        __threadfence();
        if (tid < MAXPARTS) {
            float v0 = 0.0f, v1 = 0.0f, v2 = 0.0f;
            if (tid < PARTS) {
                const unsigned gbits = *(volatile unsigned*)&g_min[b * PARTS + tid];
                if (gbits != 0u) {
                    v0 = mlen;                                            // f_velocity
                    v1 = __uint_as_float(~gbits);                         // f_min_distance
                    v2 = 6.283185307179586f * ((float)tid + 0.5f) / 8.0f; // f_direction
                }
                *(volatile unsigned*)&g_min[b * PARTS + tid] = 0u;        // reset for replay
            }
            if (tid == 0) *(volatile unsigned*)&g_cnt[b] = 0u;            // reset counter
            float* ob = out + (size_t)b * MAXPARTS * 3 + tid * 3;
            ob[0] = v0;
            ob[1] = v1;
            ob[2] = v2;
        }
    }
}

extern "C" void kernel_launch(void* const* d_in, const int* in_sizes, int n_in,
                              void* d_out, int out_size) {
    const float* seg_maps = (const float*)d_in[0];  // (128, 512, 512)
    const float* paras    = (const float*)d_in[1];  // (128, 4)
    const float* traj     = (const float*)d_in[2];  // (128, 8, 2)
    const float* cpos     = (const float*)d_in[3];  // (128, 1, 2)
    // d_in[4] = map_pos_pixel: derived analytically from the pixel index, unused
    float* out = (float*)d_out;                     // (128, 16, 3)

    const int B = in_sizes[1] / 4;                  // 128
    dim3 grid(B, SLICES);
    pcl_kernel<<<grid, CTA>>>(seg_maps, paras, traj, cpos, out);
}

// round 5
// speedup vs baseline: 2.5446x; 1.1458x over previous
#include <cuda_runtime.h>
#include <math.h>

#define NPIX 512
#define BMAX 128
#define PARTS 8
#define MAXPARTS 16
#define SLICES 4
#define CTA 256
#define INF_F 1000000000.0f
#define MU_F 1e-8f
#define THRESH 0.05f

// Cross-CTA reduction state. Zero-init at module load; self-resetting each
// launch (last CTA per batch clears after formatting). g_min stores ~bits(e),
// atomicMax: for e >= 0 float order == uint order, so max(~bits) == min(e);
// all-zero initial state means "no obstacle".
__device__ unsigned g_min[BMAX * PARTS];
__device__ unsigned g_cnt[BMAX];

// Grid (B, SLICES), 256 threads per CTA (1024 threads per batch). The batch's
// valid-disc bounding box is tiled by 4-aligned float4 pixel groups, flattened
// with an EXACT Wg-wide mapping (float-reciprocal division + fixup, no pow-2
// padding -> no wasted groups, and every group is fully in-image). Per-pixel
// bin mins go to a private smem slot sbin[bin][tid]; warp w reduces bin w and
// commits via global atomicMax. Last CTA per batch formats the output.
__global__ __launch_bounds__(CTA) void pcl_kernel(
    const float* __restrict__ seg_maps,   // (B, N, N)
    const float* __restrict__ paras,      // (B, 4): wx, wy, bx, by
    const float* __restrict__ traj,       // (B, 8, 2)
    const float* __restrict__ cpos,       // (B, 1, 2)
    float* __restrict__ out)              // (B, 16, 3)
{
    const int b    = blockIdx.x;
    const int s    = blockIdx.y;
    const int tid  = threadIdx.x;
    const int lane = tid & 31;
    const int warp = tid >> 5;            // 0..7

    __shared__ float sbin[PARTS * CTA];
    #pragma unroll
    for (int k = 0; k < PARTS; k++) sbin[k * CTA + tid] = INF_F;
    // no barrier needed: each thread reads/writes only its own column until
    // the post-loop __syncthreads()

    // scalar params (independent loads, one memory round)
    const float wx  = __ldg(&paras[b * 4 + 0]);
    const float wy  = __ldg(&paras[b * 4 + 1]);
    const float bx  = __ldg(&paras[b * 4 + 2]);
    const float by  = __ldg(&paras[b * 4 + 3]);
    const float cx  = __ldg(&cpos[b * 2 + 0]);
    const float cy  = __ldg(&cpos[b * 2 + 1]);
    const float t0x = __ldg(&traj[b * 16 + 0]);
    const float t0y = __ldg(&traj[b * 16 + 1]);
    const float t7x = __ldg(&traj[b * 16 + 14]);
    const float t7y = __ldg(&traj[b * 16 + 15]);

    // moving vector: _obs[-1]-_obs[0] == traj[7]-traj[0] (current_pos cancels)
    const float mvx  = t7x - t0x;
    const float mvy  = t7y - t0y;
    const float mlen = sqrtf(mvx * mvx + mvy * mvy);
    const float r    = 2.0f * mlen;       // VISION_RADIUS * moving_length
    const float r2   = r * r;

    // pixel-space bounding box of the disc |map_pos - c| <= r
    const int x0 = max(0, (int)floorf(bx + wx * (cx - r)) - 1);
    const int x1 = min(NPIX - 1, (int)ceilf(bx + wx * (cx + r)) + 1);
    const int y0 = max(0, (int)floorf(by + wy * (cy - r)) - 1);
    const int y1 = min(NPIX - 1, (int)ceilf(by + wy * (cy + r)) + 1);

    const float inv_wx = 1.0f / wx;
    const float inv_wy = 1.0f / wy;
    const float cxx = -bx * inv_wx - cx;  // dx = px*inv_wx + cxx
    const float cyy = -by * inv_wy - cy;  // dy = py*inv_wy + cyy

    // 4-aligned group tiling of the bbox. Since 512 % 4 == 0, aligned groups
    // never cross the image edge: y0a >= 0 and last group start <= y1 <= 511,
    // so every group load is in-bounds. Padding pixels (from alignment) lie
    // outside the disc and fail dist<=r exactly.
    const int y0a = y0 & ~3;
    int Gtot = 0, Wg = 1;
    if (x1 >= x0 && y1 >= y0) {
        Wg   = (y1 - y0a + 4) >> 2;                  // exact groups per row
        Gtot = Wg * (x1 - x0 + 1);
    }
    const float invWg = 1.0f / (float)Wg;

    const float* __restrict__ sm = seg_maps + (size_t)b * NPIX * NPIX;

    #pragma unroll 2
    for (int g = s * CTA + tid; g < Gtot; g += SLICES * CTA) {
        // exact division by Wg: float reciprocal + +/-1 fixup
        int row = __float2int_rz((float)g * invWg);
        int kq  = g - row * Wg;
        if (kq < 0)        { row--; kq += Wg; }
        else if (kq >= Wg) { row++; kq -= Wg; }

        const int px  = x0 + row;
        const int py0 = y0a + (kq << 2);

        const float4 m4 = *(const float4*)(sm + px * NPIX + py0);

        const float dx  = fmaf((float)px, inv_wx, cxx);
        const float dx2 = dx * dx;
        float dy = fmaf((float)py0, inv_wy, cyy);

        const float mm[4] = {m4.x, m4.y, m4.z, m4.w};
        #pragma unroll
        for (int j = 0; j < 4; j++) {
            const float d2 = fmaf(dy, dy, dx2);
            const float m  = mm[j];

            if (d2 <= r2 && m > THRESH) {
                const float dist = sqrtf(d2);
                if (dist <= r) {   // exact reference condition
                    const float e = __fdividef(dist + MU_F, m + MU_F);

                    // exact octant of atan2(dx, dy) mod 2pi (select chain)
                    const int bin =
                        (dy > 0.0f) ? ((dx >= 0.0f) ? ((dx <  dy) ? 0 : 1)
                                                    : ((-dx <= dy) ? 7 : 6))
                      : (dy < 0.0f) ? ((dx > 0.0f)  ? ((dx > -dy) ? 2 : 3)
                                                    : ((dx >  dy) ? 4 : 5))
                                    : ((dx > 0.0f) ? 2 : ((dx < 0.0f) ? 6 : 0));

                    float* slot = &sbin[bin * CTA + tid]; // bank==lane: conflict-free
                    *slot = fminf(*slot, e);
                }
            }
            dy += inv_wy;
        }
    }

    __syncthreads();

    // warp w reduces bin w
    {
        const float* p = &sbin[warp * CTA];
        float v = INF_F;
        #pragma unroll
        for (int c = 0; c < CTA; c += 32) v = fminf(v, p[lane + c]);
        #pragma unroll
        for (int off = 16; off > 0; off >>= 1)
            v = fminf(v, __shfl_xor_sync(0xffffffffu, v, off));
        if (lane == 0 && v < INF_F)
            atomicMax(&g_min[b * PARTS + warp], ~__float_as_uint(v));
    }

    __syncthreads();

    // arrival with acq_rel ordering: release publishes our g_min commits,
    // acquire (on the last arriver) orders its subsequent g_min reads.
    __shared__ unsigned sprev;
    if (tid == 0) {
        unsigned prev;
        asm volatile("atom.acq_rel.gpu.global.add.u32 %0, [%1], %2;"
                     : "=r"(prev) : "l"(&g_cnt[b]), "r"(1u) : "memory");
        sprev = prev;
    }
    __syncthreads();

    if (sprev == SLICES - 1) {
        if (tid < MAXPARTS) {
            float v0 = 0.0f, v1 = 0.0f, v2 = 0.0f;
            if (tid < PARTS) {
                const unsigned gbits = *(volatile unsigned*)&g_min[b * PARTS + tid];
                if (gbits != 0u) {
                    v0 = mlen;                                            // f_velocity
                    v1 = __uint_as_float(~gbits);                         // f_min_distance
                    v2 = 6.283185307179586f * ((float)tid + 0.5f) / 8.0f; // f_direction
                }
                *(volatile unsigned*)&g_min[b * PARTS + tid] = 0u;        // reset for replay
            }
            if (tid == 0) *(volatile unsigned*)&g_cnt[b] = 0u;            // reset counter
            float* ob = out + (size_t)b * MAXPARTS * 3 + tid * 3;
            ob[0] = v0;
            ob[1] = v1;
            ob[2] = v2;
        }
    }
}

extern "C" void kernel_launch(void* const* d_in, const int* in_sizes, int n_in,
                              void* d_out, int out_size) {
    const float* seg_maps = (const float*)d_in[0];  // (128, 512, 512)
    const float* paras    = (const float*)d_in[1];  // (128, 4)
    const float* traj     = (const float*)d_in[2];  // (128, 8, 2)
    const float* cpos     = (const float*)d_in[3];  // (128, 1, 2)
    // d_in[4] = map_pos_pixel: derived analytically from the pixel index, unused
    float* out = (float*)d_out;                     // (128, 16, 3)

    const int B = in_sizes[1] / 4;                  // 128
    dim3 grid(B, SLICES);
    pcl_kernel<<<grid, CTA>>>(seg_maps, paras, traj, cpos, out);
}